// round 7
// baseline (speedup 1.0000x reference)
#include <cuda_runtime.h>
#include <cuda_fp16.h>
#include <cstdint>

#define N_TOKENS 8192
#define D_MODEL  1024
#define D_FF     4096
#define TOPK     2
#define N_EXPERTS 8
#define CAP      4096
#define TOTAL    (N_TOKENS*TOPK)
#define NUM_CTAS 296          // 148 SMs x 2 CTAs

// ---------------- device scratch ----------------
__device__ int    g_cnt_raw[N_EXPERTS];
__device__ int    g_cnt[N_EXPERTS];
__device__ int    g_mtiles[N_EXPERTS];
__device__ int    g_tbase1[N_EXPERTS+1];
__device__ int    g_tbase2[N_EXPERTS+1];
__device__ int    g_rowtok[N_EXPERTS*CAP];
__device__ int    g_slotof[TOTAL];
__device__ __half g_xr [(size_t)N_TOKENS*D_MODEL];
__device__ __half g_w1t[(size_t)N_EXPERTS*D_FF*D_MODEL];
__device__ __half g_w2t[(size_t)N_EXPERTS*D_FF*D_MODEL];
__device__ __half g_w3t[(size_t)N_EXPERTS*D_MODEL*D_FF];
__device__ __half g_G  [(size_t)N_EXPERTS*CAP*D_FF];
__device__ float  g_Y  [(size_t)N_EXPERTS*CAP*D_MODEL];

// ---------------- helpers ----------------
__device__ __forceinline__ uint32_t smem_u32(const void* p){
    uint32_t a;
    asm("{ .reg .u64 t; cvta.to.shared.u64 t, %1; cvt.u32.u64 %0, t; }" : "=r"(a) : "l"(p));
    return a;
}
__device__ __forceinline__ void cp16(uint32_t s, const void* g, uint32_t n){
    asm volatile("cp.async.cg.shared.global [%0], [%1], 16, %2;" :: "r"(s), "l"(g), "r"(n));
}
#define CP_COMMIT() asm volatile("cp.async.commit_group;" ::: "memory")
#define CP_WAIT(n)  asm volatile("cp.async.wait_group %0;" :: "n"(n) : "memory")

__device__ __forceinline__ void ldsm4(uint32_t& r0, uint32_t& r1, uint32_t& r2, uint32_t& r3, uint32_t a){
    asm volatile("ldmatrix.sync.aligned.m8n8.x4.shared.b16 {%0,%1,%2,%3}, [%4];"
        : "=r"(r0), "=r"(r1), "=r"(r2), "=r"(r3) : "r"(a));
}
__device__ __forceinline__ void mma_f16(float& c0, float& c1, float& c2, float& c3,
                                        uint32_t a0, uint32_t a1, uint32_t a2, uint32_t a3,
                                        uint32_t b0, uint32_t b1){
    asm volatile("mma.sync.aligned.m16n8k16.row.col.f32.f16.f16.f32 "
        "{%0,%1,%2,%3}, {%4,%5,%6,%7}, {%8,%9}, {%0,%1,%2,%3};"
        : "+f"(c0), "+f"(c1), "+f"(c2), "+f"(c3)
        : "r"(a0), "r"(a1), "r"(a2), "r"(a3), "r"(b0), "r"(b1));
}

// smem: rows of 64 halfs = 128B, XOR swizzle on 16B segs: phys = sc ^ (row&7)
// stage = A(16K) + B(16K) = 32KB; 3 stages = 96KB
#define STAGE_B   32768
#define B_OFF     16384
#define SMEM_BYTES 98304
#define EP_PITCH  136          // staging pitch in halfs (272B: 2-way max conflicts)

// ---------------- routing ----------------
__global__ void route_init_kernel(){
    if (threadIdx.x < N_EXPERTS) g_cnt_raw[threadIdx.x] = 0;
}
__global__ void route_assign_kernel(const int* __restrict__ eidx){
    int i = blockIdx.x * blockDim.x + threadIdx.x;
    if (i >= TOTAL) return;
    int e = eidx[i] & (N_EXPERTS - 1);
    int pos = atomicAdd(&g_cnt_raw[e], 1);
    if (pos < CAP){ g_rowtok[e*CAP + pos] = i >> 1; g_slotof[i] = e*CAP + pos; }
    else g_slotof[i] = -1;
}
__global__ void route_fin_kernel(){
    if (threadIdx.x == 0){
        int b1 = 0, b2 = 0;
        for (int e = 0; e < N_EXPERTS; e++){
            int c = g_cnt_raw[e]; if (c > CAP) c = CAP;
            g_cnt[e] = c;
            int mts = (c + 127) >> 7;
            g_mtiles[e] = mts;
            g_tbase1[e] = b1; b1 += mts * (D_FF/64);
            g_tbase2[e] = b2; b2 += mts * (D_MODEL/128);
        }
        g_tbase1[N_EXPERTS] = b1;
        g_tbase2[N_EXPERTS] = b2;
    }
}
// ---------------- x -> fp16 ----------------
__global__ void round_x_kernel(const float* __restrict__ x){
    int i = blockIdx.x * blockDim.x + threadIdx.x;
    if (i >= N_TOKENS*D_MODEL/4) return;
    float4 v = ((const float4*)x)[i];
    ((__half2*)g_xr)[2*i]   = __halves2half2(__float2half_rn(v.x), __float2half_rn(v.y));
    ((__half2*)g_xr)[2*i+1] = __halves2half2(__float2half_rn(v.z), __float2half_rn(v.w));
}
// ---------------- batched transpose src[e][R][C] -> dst[e][C][R], fp16 ----------------
__global__ void transpose_kernel(const float* __restrict__ src, int sel, int R, int C){
    __shared__ float tile[32][33];
    __half* dstb = (sel == 0) ? g_w1t : (sel == 1) ? g_w2t : g_w3t;
    int e = blockIdx.z;
    const float* s = src + (size_t)e*R*C;
    __half* d = dstb + (size_t)e*R*C;
    int bx = blockIdx.x, by = blockIdx.y;
    int tx = threadIdx.x & 31, ty = threadIdx.x >> 5;
    #pragma unroll
    for (int i = 0; i < 32; i += 8)
        tile[ty + i][tx] = s[(size_t)(by*32 + ty + i) * C + bx*32 + tx];
    __syncthreads();
    #pragma unroll
    for (int i = 0; i < 32; i += 8)
        d[(size_t)(bx*32 + ty + i) * R + by*32 + tx] = __float2half_rn(tile[tx][ty + i]);
}

// ---------------- persistent fp16 mma.sync GEMM: CTA 128x128, 4 warps 64x64 ----------------
// MODE 0: [h1|h2] = Xg @ interleaved[w1t,w2t]^T, SwiGLU -> g_G  (tiles: mt fastest)
// MODE 1: Y = G @ w3t^T -> g_Y                                  (tiles: nt fastest)
template<int MODE>
__global__ void __launch_bounds__(128, 2) gemm_kernel(){
    const int NCH = (MODE == 0) ? (D_MODEL/64) : (D_FF/64);
    extern __shared__ char smem[];
    uint32_t sbase = smem_u32(smem);

    int tid = threadIdx.x;
    int wid = tid >> 5, lid = tid & 31;
    int wm = wid >> 1, wn = wid & 1;          // 2x2 warps, warp tile 64x64
    int g = lid >> 2, t = lid & 3;
    int r0 = tid >> 3;                         // cp rows 0..15 (+16*it)
    int sc = tid & 7;                          // 16B segment

    // tile-independent smem addressing
    uint32_t adst[8], bdst[8];
    #pragma unroll
    for (int it = 0; it < 8; it++){
        uint32_t row = (uint32_t)(r0 + it*16);
        uint32_t seg = ((uint32_t)sc ^ (row & 7u)) << 4;
        adst[it] = sbase + row*128u + seg;
        bdst[it] = sbase + B_OFF + row*128u + seg;
    }
    uint32_t albase[4], blbase[4];
    #pragma unroll
    for (int mf = 0; mf < 4; mf++){
        uint32_t row = (uint32_t)(wm*64 + mf*16 + (lid & 15));
        albase[mf] = sbase + row*128u + ((row & 7u) << 4);
    }
    #pragma unroll
    for (int j = 0; j < 4; j++){
        uint32_t row = (uint32_t)(wn*64 + j*16 + (lid & 7) + ((lid >> 4) & 1)*8);
        blbase[j] = sbase + B_OFF + row*128u + ((row & 7u) << 4);
    }
    uint32_t a_sl_hi = (uint32_t)(lid >> 4);
    uint32_t b_sl_hi = (uint32_t)((lid >> 3) & 1);

    const int* tb = (MODE == 0) ? g_tbase1 : g_tbase2;
    int total = __ldg(&tb[N_EXPERTS]);

    for (int tile = blockIdx.x; tile < total; tile += gridDim.x){
        int e = 0;
        while (__ldg(&tb[e+1]) <= tile) e++;
        int local = tile - __ldg(&tb[e]);
        int mts = __ldg(&g_mtiles[e]);
        int cnt = __ldg(&g_cnt[e]);
        int mt, nt;
        if (MODE == 0){ mt = local % mts; nt = local / mts; }
        else          { nt = local & 7;  mt = local >> 3; }

        // ---- per-tile source descriptors ----
        const char* abase;
        uint32_t aoff[8];
        uint32_t amask = 0;
        const __half* bbase;
        size_t bstride;
        if (MODE == 0){
            abase = (const char*)g_xr;
            #pragma unroll
            for (int it = 0; it < 8; it++){
                int grow = mt*128 + r0 + it*16;
                int tok = (grow < cnt) ? g_rowtok[e*CAP + grow] : -1;
                aoff[it] = (tok >= 0) ? ((uint32_t)tok*(D_MODEL*2) + sc*16) : 0;
                if (tok >= 0) amask |= (1u << it);
            }
            const __half* wb = (r0 & 1) ? g_w2t : g_w1t;
            bbase = wb + ((size_t)e*D_FF + nt*64 + (r0 >> 1))*D_MODEL + sc*8;
            bstride = (size_t)8*D_MODEL;
        } else {
            abase = (const char*)(g_G + ((size_t)(e*CAP + mt*128 + r0))*D_FF + sc*8);
            #pragma unroll
            for (int it = 0; it < 8; it++){ aoff[it] = (uint32_t)it*16*D_FF*2; amask |= (1u<<it); }
            bbase = g_w3t + ((size_t)e*D_MODEL + nt*128 + r0)*D_FF + sc*8;
            bstride = (size_t)16*D_FF;
        }

        float c[4][8][4];
        #pragma unroll
        for (int mf = 0; mf < 4; mf++)
            #pragma unroll
            for (int nf = 0; nf < 8; nf++)
                #pragma unroll
                for (int i = 0; i < 4; i++) c[mf][nf][i] = 0.f;

        // ---- prologue: chunks 0,1 -> stages 0,1 ----
        #pragma unroll
        for (int pc = 0; pc < 2; pc++){
            uint32_t so = pc*STAGE_B;
            #pragma unroll
            for (int it = 0; it < 8; it++){
                cp16(adst[it] + so, abase + aoff[it] + (size_t)pc*128, ((amask>>it)&1) ? 16u : 0u);
                cp16(bdst[it] + so, bbase + (size_t)it*bstride + pc*64, 16u);
            }
            CP_COMMIT();
        }

        #pragma unroll 1
        for (int kc = 0; kc < NCH; kc++){
            if (kc == NCH-1) { CP_WAIT(0); } else { CP_WAIT(1); }
            __syncthreads();
            if (kc + 2 < NCH){
                uint32_t so = ((kc+2)%3)*STAGE_B;
                #pragma unroll
                for (int it = 0; it < 8; it++){
                    cp16(adst[it] + so, abase + aoff[it] + (size_t)(kc+2)*128, ((amask>>it)&1) ? 16u : 0u);
                    cp16(bdst[it] + so, bbase + (size_t)it*bstride + (size_t)(kc+2)*64, 16u);
                }
                CP_COMMIT();
            }
            uint32_t so = (kc%3)*STAGE_B;
            #pragma unroll
            for (int kk = 0; kk < 4; kk++){
                uint32_t a[4][4];
                #pragma unroll
                for (int mf = 0; mf < 4; mf++){
                    uint32_t sl = (uint32_t)(2*kk) + a_sl_hi;
                    ldsm4(a[mf][0], a[mf][1], a[mf][2], a[mf][3], (albase[mf] ^ (sl<<4)) + so);
                }
                uint32_t b[8][2];
                #pragma unroll
                for (int j = 0; j < 4; j++){
                    uint32_t sl = (uint32_t)(2*kk) + b_sl_hi;
                    ldsm4(b[2*j][0], b[2*j][1], b[2*j+1][0], b[2*j+1][1], (blbase[j] ^ (sl<<4)) + so);
                }
                #pragma unroll
                for (int mf = 0; mf < 4; mf++)
                    #pragma unroll
                    for (int nf = 0; nf < 8; nf++)
                        mma_f16(c[mf][nf][0], c[mf][nf][1], c[mf][nf][2], c[mf][nf][3],
                                a[mf][0], a[mf][1], a[mf][2], a[mf][3],
                                b[nf][0], b[nf][1]);
            }
        }

        // ---- epilogue ----
        if (MODE == 0){
            // stage SwiGLU result through smem for coalesced 16B stores
            __syncthreads();                       // all warps done reading stages
            __half* ep = (__half*)smem;
            #pragma unroll
            for (int mf = 0; mf < 4; mf++){
                #pragma unroll
                for (int i2 = 0; i2 < 2; i2++){
                    int mrow = wm*64 + mf*16 + i2*8 + g;
                    __half* er = ep + mrow*EP_PITCH + wn*32;
                    #pragma unroll
                    for (int nf = 0; nf < 8; nf++){
                        float h = c[mf][nf][i2*2 + 0];
                        float v = c[mf][nf][i2*2 + 1];
                        er[nf*4 + t] = __float2half_rn(h * v / (1.f + __expf(-h)));
                    }
                }
            }
            __syncthreads();
            __half* gd = g_G + ((size_t)(e*CAP + mt*128 + tid))*D_FF + nt*64;
            const __half* er = ep + tid*EP_PITCH;
            #pragma unroll
            for (int j = 0; j < 8; j++)
                *(float4*)(gd + j*8) = *(const float4*)(er + j*8);
        } else {
            #pragma unroll
            for (int mf = 0; mf < 4; mf++){
                #pragma unroll
                for (int i2 = 0; i2 < 2; i2++){
                    int m = mt*128 + wm*64 + mf*16 + i2*8 + g;
                    float* yd = g_Y + ((size_t)(e*CAP + m))*D_MODEL + nt*128 + wn*64;
                    #pragma unroll
                    for (int nf = 0; nf < 8; nf++){
                        float2 o = make_float2(c[mf][nf][i2*2 + 0], c[mf][nf][i2*2 + 1]);
                        *(float2*)(yd + nf*8 + 2*t) = o;
                    }
                }
            }
        }
        __syncthreads();   // protect stages/staging before next tile's prologue
    }
}

// ---------------- weighted top-k combine ----------------
__global__ void combine_kernel(const float* __restrict__ ew, float* __restrict__ out){
    int i = blockIdx.x * blockDim.x + threadIdx.x;
    if (i >= N_TOKENS*D_MODEL/4) return;
    int tok = i >> 8;
    int d4 = i & 255;
    float4 acc = make_float4(0.f,0.f,0.f,0.f);
    #pragma unroll
    for (int k = 0; k < TOPK; k++){
        int s = g_slotof[2*tok + k];
        if (s >= 0){
            float w = ew[2*tok + k];
            float4 v = ((const float4*)g_Y)[(size_t)s*(D_MODEL/4) + d4];
            acc.x += w*v.x; acc.y += w*v.y; acc.z += w*v.z; acc.w += w*v.w;
        }
    }
    ((float4*)out)[i] = acc;
}

extern "C" void kernel_launch(void* const* d_in, const int* in_sizes, int n_in,
                              void* d_out, int out_size) {
    const float* x   = (const float*)d_in[0];
    const int*   idx = (const int*)  d_in[1];
    const float* ew  = (const float*)d_in[2];
    const float* w1  = (const float*)d_in[3];
    const float* w2  = (const float*)d_in[4];
    const float* w3  = (const float*)d_in[5];
    float* out = (float*)d_out;

    cudaFuncSetAttribute(gemm_kernel<0>, cudaFuncAttributeMaxDynamicSharedMemorySize, SMEM_BYTES);
    cudaFuncSetAttribute(gemm_kernel<1>, cudaFuncAttributeMaxDynamicSharedMemorySize, SMEM_BYTES);

    route_init_kernel<<<1, 32>>>();
    route_assign_kernel<<<TOTAL/256, 256>>>(idx);
    route_fin_kernel<<<1, 32>>>();
    round_x_kernel<<<(N_TOKENS*D_MODEL/4)/256, 256>>>(x);

    transpose_kernel<<<dim3(D_FF/32,    D_MODEL/32, N_EXPERTS), 256>>>(w1, 0, D_MODEL, D_FF);
    transpose_kernel<<<dim3(D_FF/32,    D_MODEL/32, N_EXPERTS), 256>>>(w2, 1, D_MODEL, D_FF);
    transpose_kernel<<<dim3(D_MODEL/32, D_FF/32,    N_EXPERTS), 256>>>(w3, 2, D_FF, D_MODEL);

    gemm_kernel<0><<<NUM_CTAS, 128, SMEM_BYTES>>>();
    gemm_kernel<1><<<NUM_CTAS, 128, SMEM_BYTES>>>();

    combine_kernel<<<(N_TOKENS*D_MODEL/4)/256, 256>>>(ew, out);
}

// round 8
// speedup vs baseline: 1.0872x; 1.0872x over previous
#include <cuda_runtime.h>
#include <cuda_fp16.h>
#include <cstdint>

#define N_TOKENS 8192
#define D_MODEL  1024
#define D_FF     4096
#define TOPK     2
#define N_EXPERTS 8
#define CAP      4096
#define TOTAL    (N_TOKENS*TOPK)

// ---------------- device scratch ----------------
__device__ int    g_cnt_raw[N_EXPERTS];
__device__ int    g_cnt[N_EXPERTS];
__device__ int    g_rowtok[N_EXPERTS*CAP];
__device__ int    g_slotof[TOTAL];
__device__ __half g_xr [(size_t)N_TOKENS*D_MODEL];
__device__ __half g_w1t[(size_t)N_EXPERTS*D_FF*D_MODEL];
__device__ __half g_w2t[(size_t)N_EXPERTS*D_FF*D_MODEL];
__device__ __half g_w3t[(size_t)N_EXPERTS*D_MODEL*D_FF];
__device__ __half g_G  [(size_t)N_EXPERTS*CAP*D_FF];
__device__ float  g_Y  [(size_t)N_EXPERTS*CAP*D_MODEL];

// ---------------- helpers ----------------
__device__ __forceinline__ uint32_t smem_u32(const void* p){
    uint32_t a;
    asm("{ .reg .u64 t; cvta.to.shared.u64 t, %1; cvt.u32.u64 %0, t; }" : "=r"(a) : "l"(p));
    return a;
}
__device__ __forceinline__ void cp16(uint32_t s, const void* g, uint32_t n){
    asm volatile("cp.async.cg.shared.global [%0], [%1], 16, %2;" :: "r"(s), "l"(g), "r"(n));
}
#define CP_COMMIT() asm volatile("cp.async.commit_group;" ::: "memory")
#define CP_WAIT(n)  asm volatile("cp.async.wait_group %0;" :: "n"(n) : "memory")

__device__ __forceinline__ void ldsm4(uint32_t& r0, uint32_t& r1, uint32_t& r2, uint32_t& r3, uint32_t a){
    asm volatile("ldmatrix.sync.aligned.m8n8.x4.shared.b16 {%0,%1,%2,%3}, [%4];"
        : "=r"(r0), "=r"(r1), "=r"(r2), "=r"(r3) : "r"(a));
}
__device__ __forceinline__ void mma_f16(float& c0, float& c1, float& c2, float& c3,
                                        uint32_t a0, uint32_t a1, uint32_t a2, uint32_t a3,
                                        uint32_t b0, uint32_t b1){
    asm volatile("mma.sync.aligned.m16n8k16.row.col.f32.f16.f16.f32 "
        "{%0,%1,%2,%3}, {%4,%5,%6,%7}, {%8,%9}, {%0,%1,%2,%3};"
        : "+f"(c0), "+f"(c1), "+f"(c2), "+f"(c3)
        : "r"(a0), "r"(a1), "r"(a2), "r"(a3), "r"(b0), "r"(b1));
}

// smem: rows of 64 halfs = 128B, XOR swizzle on 16B segs: phys = sc ^ (row&7)
// stage = A(16K) + B(16K) = 32KB; 3 stages = 96KB
#define STAGE_B   32768
#define B_OFF     16384
#define SMEM_BYTES 98304
#define EP_PITCH  136          // epilogue staging pitch in halfs (conflict-free)

// ---------------- routing ----------------
__global__ void route_init_kernel(){
    if (threadIdx.x < N_EXPERTS) g_cnt_raw[threadIdx.x] = 0;
}
__global__ void route_assign_kernel(const int* __restrict__ eidx){
    int i = blockIdx.x * blockDim.x + threadIdx.x;
    if (i >= TOTAL) return;
    int e = eidx[i] & (N_EXPERTS - 1);
    int pos = atomicAdd(&g_cnt_raw[e], 1);
    if (pos < CAP){ g_rowtok[e*CAP + pos] = i >> 1; g_slotof[i] = e*CAP + pos; }
    else g_slotof[i] = -1;
}
__global__ void route_fin_kernel(){
    if (threadIdx.x < N_EXPERTS){
        int c = g_cnt_raw[threadIdx.x];
        g_cnt[threadIdx.x] = c < CAP ? c : CAP;
    }
}
// ---------------- x -> fp16 ----------------
__global__ void round_x_kernel(const float* __restrict__ x){
    int i = blockIdx.x * blockDim.x + threadIdx.x;
    if (i >= N_TOKENS*D_MODEL/4) return;
    float4 v = ((const float4*)x)[i];
    ((__half2*)g_xr)[2*i]   = __halves2half2(__float2half_rn(v.x), __float2half_rn(v.y));
    ((__half2*)g_xr)[2*i+1] = __halves2half2(__float2half_rn(v.z), __float2half_rn(v.w));
}
// ---------------- batched transpose src[e][R][C] -> dst[e][C][R], fp16, half2-coalesced ----------------
// block: 256 thr, src tile 64(rows) x 32(cols) -> dst 32 x 64
__global__ void transpose_kernel(const float* __restrict__ src, int sel, int R, int C){
    __shared__ float tile[64][33];
    __half* dstb = (sel == 0) ? g_w1t : (sel == 1) ? g_w2t : g_w3t;
    int e = blockIdx.z;
    const float* s = src + (size_t)e*R*C;
    __half* d = dstb + (size_t)e*R*C;
    int r0 = blockIdx.y*64, c0 = blockIdx.x*32;
    int tx = threadIdx.x & 31, ty = threadIdx.x >> 5;    // ty 0..7
    #pragma unroll
    for (int i = 0; i < 64; i += 8)
        tile[ty + i][tx] = s[(size_t)(r0 + ty + i) * C + c0 + tx];
    __syncthreads();
    #pragma unroll
    for (int it = 0; it < 4; it++){
        int j = ty*4 + it;                               // dst row c0+j
        __half2 v = __halves2half2(__float2half_rn(tile[2*tx][j]),
                                   __float2half_rn(tile[2*tx+1][j]));
        ((__half2*)(d + (size_t)(c0 + j)*R + r0))[tx] = v;
    }
}

// ---------------- fp16 mma.sync GEMM: CTA 128x128, 4 warps (2x2) of 64x64 ----------------
// MODE 0: [h1|h2] = Xg @ interleaved[w1t,w2t]^T, SwiGLU -> g_G. grid (64, 32, 8)
// MODE 1: Y = G @ w3t^T -> g_Y.                                 grid (8, 32, 8)
template<int MODE>
__global__ void __launch_bounds__(128, 2) gemm_kernel(){
    const int NCH = (MODE == 0) ? (D_MODEL/64) : (D_FF/64);
    int nt = blockIdx.x, mt = blockIdx.y, e = blockIdx.z;
    int cnt = g_cnt[e];
    if (mt*128 >= cnt) return;
    extern __shared__ char smem[];
    uint32_t sbase = smem_u32(smem);

    int tid = threadIdx.x;
    int wid = tid >> 5, lid = tid & 31;
    int wm = wid >> 1, wn = wid & 1;          // 2x2 warps, warp tile 64(m) x 64(n)
    int g = lid >> 2, t = lid & 3;

    int r0 = tid >> 3;                         // 0..15
    int sc = tid & 7;                          // 16B segment
    const char* abase;
    uint32_t aoff[8];
    uint32_t amask = 0;
    const __half* bbase;
    size_t bstride;
    if (MODE == 0){
        abase = (const char*)g_xr;
        #pragma unroll
        for (int it = 0; it < 8; it++){
            int grow = mt*128 + r0 + it*16;
            int tok = (grow < cnt) ? g_rowtok[e*CAP + grow] : -1;
            aoff[it] = (tok >= 0) ? ((uint32_t)tok*(D_MODEL*2) + sc*16) : 0;
            if (tok >= 0) amask |= (1u << it);
        }
        const __half* wb = (r0 & 1) ? g_w2t : g_w1t;
        bbase = wb + ((size_t)e*D_FF + nt*64 + (r0 >> 1))*D_MODEL + sc*8;
        bstride = (size_t)8*D_MODEL;
    } else {
        abase = (const char*)(g_G + ((size_t)(e*CAP + mt*128 + r0))*D_FF + sc*8);
        #pragma unroll
        for (int it = 0; it < 8; it++){ aoff[it] = (uint32_t)it*16*D_FF*2; amask |= (1u<<it); }
        bbase = g_w3t + ((size_t)e*D_MODEL + nt*128 + r0)*D_FF + sc*8;
        bstride = (size_t)16*D_FF;
    }
    uint32_t adst[8], bdst[8];
    #pragma unroll
    for (int it = 0; it < 8; it++){
        uint32_t row = (uint32_t)(r0 + it*16);
        uint32_t seg = ((uint32_t)sc ^ (row & 7u)) << 4;
        adst[it] = sbase + row*128u + seg;
        bdst[it] = sbase + B_OFF + row*128u + seg;
    }
    uint32_t albase[4], blbase[4];
    #pragma unroll
    for (int mf = 0; mf < 4; mf++){
        uint32_t row = (uint32_t)(wm*64 + mf*16 + (lid & 15));
        albase[mf] = sbase + row*128u + ((row & 7u) << 4);
    }
    #pragma unroll
    for (int j = 0; j < 4; j++){
        uint32_t row = (uint32_t)(wn*64 + j*16 + (lid & 7) + ((lid >> 4) & 1)*8);
        blbase[j] = sbase + B_OFF + row*128u + ((row & 7u) << 4);
    }
    uint32_t a_sl_hi = (uint32_t)(lid >> 4);
    uint32_t b_sl_hi = (uint32_t)((lid >> 3) & 1);

    float c[4][8][4];
    #pragma unroll
    for (int mf = 0; mf < 4; mf++)
        #pragma unroll
        for (int nf = 0; nf < 8; nf++)
            #pragma unroll
            for (int i = 0; i < 4; i++) c[mf][nf][i] = 0.f;

    // ---- prologue: chunks 0,1 into stages 0,1 ----
    #pragma unroll
    for (int pc = 0; pc < 2; pc++){
        uint32_t so = pc*STAGE_B;
        #pragma unroll
        for (int it = 0; it < 8; it++){
            cp16(adst[it] + so, abase + aoff[it] + (size_t)pc*128, ((amask>>it)&1) ? 16u : 0u);
            cp16(bdst[it] + so, bbase + (size_t)it*bstride + pc*64, 16u);
        }
        CP_COMMIT();
    }

    #pragma unroll 1
    for (int kc = 0; kc < NCH; kc++){
        if (kc == NCH-1) { CP_WAIT(0); } else { CP_WAIT(1); }
        __syncthreads();
        if (kc + 2 < NCH){
            uint32_t so = ((kc+2)%3)*STAGE_B;
            #pragma unroll
            for (int it = 0; it < 8; it++){
                cp16(adst[it] + so, abase + aoff[it] + (size_t)(kc+2)*128, ((amask>>it)&1) ? 16u : 0u);
                cp16(bdst[it] + so, bbase + (size_t)it*bstride + (size_t)(kc+2)*64, 16u);
            }
            CP_COMMIT();
        }
        uint32_t so = (kc%3)*STAGE_B;
        #pragma unroll
        for (int kk = 0; kk < 4; kk++){
            uint32_t a[4][4];
            #pragma unroll
            for (int mf = 0; mf < 4; mf++){
                uint32_t sl = (uint32_t)(2*kk) + a_sl_hi;
                ldsm4(a[mf][0], a[mf][1], a[mf][2], a[mf][3], (albase[mf] ^ (sl<<4)) + so);
            }
            uint32_t b[8][2];
            #pragma unroll
            for (int j = 0; j < 4; j++){
                uint32_t sl = (uint32_t)(2*kk) + b_sl_hi;
                ldsm4(b[2*j][0], b[2*j][1], b[2*j+1][0], b[2*j+1][1], (blbase[j] ^ (sl<<4)) + so);
            }
            #pragma unroll
            for (int mf = 0; mf < 4; mf++)
                #pragma unroll
                for (int nf = 0; nf < 8; nf++)
                    mma_f16(c[mf][nf][0], c[mf][nf][1], c[mf][nf][2], c[mf][nf][3],
                            a[mf][0], a[mf][1], a[mf][2], a[mf][3],
                            b[nf][0], b[nf][1]);
        }
    }

    // ---- epilogue ----
    if (MODE == 0){
        // stage SwiGLU through smem, then fully-coalesced 128B-row stores
        __syncthreads();                        // all warps done with stages
        __half* ep = (__half*)smem;
        #pragma unroll
        for (int mf = 0; mf < 4; mf++){
            #pragma unroll
            for (int i2 = 0; i2 < 2; i2++){
                int mrow = wm*64 + mf*16 + i2*8 + g;
                __half* er = ep + mrow*EP_PITCH + wn*32;
                #pragma unroll
                for (int nf = 0; nf < 8; nf++){
                    float h = c[mf][nf][i2*2 + 0];
                    float v = c[mf][nf][i2*2 + 1];
                    er[nf*4 + t] = __float2half_rn(h * v / (1.f + __expf(-h)));
                }
            }
        }
        __syncthreads();
        int g8 = tid >> 3, sl = tid & 7;        // 16 groups x 8 lanes
        #pragma unroll
        for (int j = 0; j < 8; j++){
            int row = g8*8 + j;
            float4 v = *(const float4*)(ep + row*EP_PITCH + sl*8);
            *(float4*)(g_G + ((size_t)(e*CAP + mt*128 + row))*D_FF + nt*64 + sl*8) = v;
        }
    } else {
        #pragma unroll
        for (int mf = 0; mf < 4; mf++){
            #pragma unroll
            for (int i2 = 0; i2 < 2; i2++){
                int m = mt*128 + wm*64 + mf*16 + i2*8 + g;
                float* yd = g_Y + ((size_t)(e*CAP + m))*D_MODEL + nt*128 + wn*64;
                #pragma unroll
                for (int nf = 0; nf < 8; nf++){
                    float2 o = make_float2(c[mf][nf][i2*2 + 0], c[mf][nf][i2*2 + 1]);
                    *(float2*)(yd + nf*8 + 2*t) = o;
                }
            }
        }
    }
}

// ---------------- weighted top-k combine ----------------
__global__ void combine_kernel(const float* __restrict__ ew, float* __restrict__ out){
    int i = blockIdx.x * blockDim.x + threadIdx.x;
    if (i >= N_TOKENS*D_MODEL/4) return;
    int tok = i >> 8;
    int d4 = i & 255;
    float4 acc = make_float4(0.f,0.f,0.f,0.f);
    #pragma unroll
    for (int k = 0; k < TOPK; k++){
        int s = g_slotof[2*tok + k];
        if (s >= 0){
            float w = ew[2*tok + k];
            float4 v = ((const float4*)g_Y)[(size_t)s*(D_MODEL/4) + d4];
            acc.x += w*v.x; acc.y += w*v.y; acc.z += w*v.z; acc.w += w*v.w;
        }
    }
    ((float4*)out)[i] = acc;
}

extern "C" void kernel_launch(void* const* d_in, const int* in_sizes, int n_in,
                              void* d_out, int out_size) {
    const float* x   = (const float*)d_in[0];
    const int*   idx = (const int*)  d_in[1];
    const float* ew  = (const float*)d_in[2];
    const float* w1  = (const float*)d_in[3];
    const float* w2  = (const float*)d_in[4];
    const float* w3  = (const float*)d_in[5];
    float* out = (float*)d_out;

    cudaFuncSetAttribute(gemm_kernel<0>, cudaFuncAttributeMaxDynamicSharedMemorySize, SMEM_BYTES);
    cudaFuncSetAttribute(gemm_kernel<1>, cudaFuncAttributeMaxDynamicSharedMemorySize, SMEM_BYTES);

    route_init_kernel<<<1, 32>>>();
    route_assign_kernel<<<TOTAL/256, 256>>>(idx);
    route_fin_kernel<<<1, 32>>>();
    round_x_kernel<<<(N_TOKENS*D_MODEL/4)/256, 256>>>(x);

    // w1,w2: src 1024x4096 -> tiles (64r x 32c): grid (128, 16, 8)
    transpose_kernel<<<dim3(D_FF/32,    D_MODEL/64, N_EXPERTS), 256>>>(w1, 0, D_MODEL, D_FF);
    transpose_kernel<<<dim3(D_FF/32,    D_MODEL/64, N_EXPERTS), 256>>>(w2, 1, D_MODEL, D_FF);
    // w3: src 4096x1024: grid (32, 64, 8)
    transpose_kernel<<<dim3(D_MODEL/32, D_FF/64,    N_EXPERTS), 256>>>(w3, 2, D_FF, D_MODEL);

    gemm_kernel<0><<<dim3(D_FF/64,     CAP/128, N_EXPERTS), 128, SMEM_BYTES>>>();
    gemm_kernel<1><<<dim3(D_MODEL/128, CAP/128, N_EXPERTS), 128, SMEM_BYTES>>>();

    combine_kernel<<<(N_TOKENS*D_MODEL/4)/256, 256>>>(ew, out);
}